// round 2
// baseline (speedup 1.0000x reference)
#include <cuda_runtime.h>
#include <cstdint>

#define BATCH 64
#define SEQ   512
#define DIN   512
#define MEM   256
#define HID   512

// ------------------------- device scratch (no allocs allowed) ----------------
__device__ float g_u[BATCH * SEQ];          // u[b][t]
__device__ float g_HT[SEQ * MEM];           // HT[t][k] = (A^t B)[k]
__device__ float g_P0[MEM * MEM];           // ping-pong for A^(2^i)
__device__ float g_P1[MEM * MEM];
__device__ float g_G[SEQ * HID];            // G = HT @ Wh_m   (512 x 512)

// ---------------- u = relu(x @ Wu_w + Wu_b), one warp per (b,t) --------------
__global__ void k_u(const float* __restrict__ x, const float* __restrict__ w,
                    const float* __restrict__ bias)
{
    int warp = (blockIdx.x * blockDim.x + threadIdx.x) >> 5;
    int lane = threadIdx.x & 31;
    if (warp >= BATCH * SEQ) return;
    const float4* xr = reinterpret_cast<const float4*>(x) + (size_t)warp * (DIN / 4);
    const float4* wr = reinterpret_cast<const float4*>(w);
    float acc = 0.f;
#pragma unroll
    for (int i = 0; i < DIN / 4 / 32; i++) {
        float4 a = xr[lane + i * 32];
        float4 b = wr[lane + i * 32];
        acc += a.x * b.x + a.y * b.y + a.z * b.z + a.w * b.w;
    }
#pragma unroll
    for (int off = 16; off; off >>= 1) acc += __shfl_xor_sync(0xffffffffu, acc, off);
    if (lane == 0) g_u[warp] = fmaxf(acc + bias[0], 0.f);
}

// ---------------- copy A into g_P0; HT[0] = B --------------------------------
__global__ void k_init(const float* __restrict__ A, const float* __restrict__ Bv)
{
    int i = blockIdx.x * blockDim.x + threadIdx.x;
    if (i < MEM * MEM) g_P0[i] = A[i];
    if (i < MEM) g_HT[i] = Bv[i];
}

// ---------------- HT[c+r] = P @ HT[r],  P = g_P0 or g_P1 ---------------------
__global__ void k_extend(int which, int c)
{
    const float* __restrict__ P = which ? g_P1 : g_P0;
    __shared__ float s[MEM];
    int r = blockIdx.x;          // 0..c-1
    int i = threadIdx.x;         // 0..255
    s[i] = g_HT[r * MEM + i];
    __syncthreads();
    const float* Prow = P + i * MEM;
    float acc = 0.f;
#pragma unroll 8
    for (int l = 0; l < MEM; l++) acc = fmaf(Prow[l], s[l], acc);
    g_HT[(c + r) * MEM + i] = acc;
}

// ---------------- 64x64-tile f32 GEMM core (device inline) -------------------
__device__ __forceinline__ void mm_tile(
    const float* __restrict__ A, int lda,
    const float* __restrict__ B, int ldb,
    float* __restrict__ C, int ldc, int K,
    int m0, int n0)
{
    __shared__ float As[16][68];
    __shared__ float Bs[16][68];
    int tx = threadIdx.x & 15, ty = threadIdx.x >> 4;
    float acc[4][4] = {};
    for (int k0 = 0; k0 < K; k0 += 16) {
#pragma unroll
        for (int l = threadIdx.x; l < 64 * 16; l += 256) {
            int m = l >> 4, k = l & 15;
            As[k][m] = A[(size_t)(m0 + m) * lda + k0 + k];
        }
#pragma unroll
        for (int l = threadIdx.x; l < 16 * 64; l += 256) {
            int k = l >> 6, n = l & 63;
            Bs[k][n] = B[(size_t)(k0 + k) * ldb + n0 + n];
        }
        __syncthreads();
#pragma unroll
        for (int kk = 0; kk < 16; kk++) {
            float a[4], b[4];
#pragma unroll
            for (int i = 0; i < 4; i++) a[i] = As[kk][ty * 4 + i];
#pragma unroll
            for (int j = 0; j < 4; j++) b[j] = Bs[kk][tx * 4 + j];
#pragma unroll
            for (int i = 0; i < 4; i++)
#pragma unroll
                for (int j = 0; j < 4; j++)
                    acc[i][j] = fmaf(a[i], b[j], acc[i][j]);
        }
        __syncthreads();
    }
#pragma unroll
    for (int i = 0; i < 4; i++)
#pragma unroll
        for (int j = 0; j < 4; j++)
            C[(size_t)(m0 + ty * 4 + i) * ldc + n0 + tx * 4 + j] = acc[i][j];
}

// ---------------- square: dst = P @ P (ping-pong on selector) ----------------
__global__ __launch_bounds__(256) void k_sq(int src_which)
{
    const float* P = src_which ? g_P1 : g_P0;
    float* D       = src_which ? g_P0 : g_P1;
    mm_tile(P, MEM, P, MEM, D, MEM, MEM, blockIdx.y * 64, blockIdx.x * 64);
}

// ---------------- G = HT (512x256) @ Wh_w[0:256,:] (256x512) -----------------
__global__ __launch_bounds__(256) void k_G(const float* __restrict__ Wh_w)
{
    mm_tile(g_HT, MEM, Wh_w, HID, g_G, HID, MEM, blockIdx.y * 64, blockIdx.x * 64);
}

// ---------------- fused big GEMM ---------------------------------------------
// h[b] = relu( [Toeplitz(u_b) | x_b] (512x1024) @ [G ; Wh_x] (1024x512) + bias )
// Tile 128x128, BK=16, 256 threads, 8x8 micro-tile.
// Toeplitz half reads straight from zero-padded s_u (no A staging, causal skip).
__global__ __launch_bounds__(256) void k_big(
    const float* __restrict__ x,
    const float* __restrict__ Wh_w,
    const float* __restrict__ Wh_b,
    float* __restrict__ out, int write_hn)
{
    __shared__ float s_u[1024];       // s_u[512+d] = u[b][d]; [0,512) zeros
    __shared__ float Bs[16][128];
    __shared__ float As[16][132];     // x-phase A tile (transposed)

    int bat = blockIdx.z;
    int t0  = blockIdx.y * 128;
    int n0  = blockIdx.x * 128;
    int tid = threadIdx.x;
    int tx = tid & 15, ty = tid >> 4;

    for (int i = tid; i < 512; i += 256) {
        s_u[i]       = 0.f;
        s_u[512 + i] = g_u[bat * SEQ + i];
    }

    float acc[8][8];
#pragma unroll
    for (int i = 0; i < 8; i++)
#pragma unroll
        for (int j = 0; j < 8; j++) acc[i][j] = 0.f;

    __syncthreads();

    // -------- Phase 1: Toeplitz(u) @ G, causal K range [0, t0+128) ----------
    int K1 = t0 + 128;                // == min(512, t0+128) since t0 <= 384
    for (int k0 = 0; k0 < K1; k0 += 16) {
#pragma unroll
        for (int v = 0; v < 2; v++) {
            int idx = tid + v * 256;  // 0..511 float4 slots
            int k = idx >> 5, nq = idx & 31;
            *reinterpret_cast<float4*>(&Bs[k][nq * 4]) =
                *reinterpret_cast<const float4*>(&g_G[(size_t)(k0 + k) * HID + n0 + nq * 4]);
        }
        __syncthreads();
#pragma unroll
        for (int kk = 0; kk < 16; kk++) {
            int base = 512 + t0 - k0 - kk;
            float a[8];
#pragma unroll
            for (int i = 0; i < 4; i++) {
                a[i]     = s_u[base + ty * 4 + i];
                a[4 + i] = s_u[base + 64 + ty * 4 + i];
            }
            float4 b0 = *reinterpret_cast<const float4*>(&Bs[kk][tx * 4]);
            float4 b1 = *reinterpret_cast<const float4*>(&Bs[kk][64 + tx * 4]);
            float bb[8] = {b0.x, b0.y, b0.z, b0.w, b1.x, b1.y, b1.z, b1.w};
#pragma unroll
            for (int i = 0; i < 8; i++)
#pragma unroll
                for (int j = 0; j < 8; j++)
                    acc[i][j] = fmaf(a[i], bb[j], acc[i][j]);
        }
        __syncthreads();
    }

    // -------- Phase 2: x @ Wh_x, K in [512, 1024) ---------------------------
    for (int k0 = 512; k0 < 1024; k0 += 16) {
#pragma unroll
        for (int v = 0; v < 2; v++) {
            int idx = tid + v * 256;  // 0..511
            int t = idx >> 2, kq = idx & 3;
            float4 val = *reinterpret_cast<const float4*>(
                &x[((size_t)(bat * SEQ) + t0 + t) * DIN + (k0 - 512) + kq * 4]);
            As[kq * 4 + 0][t] = val.x;
            As[kq * 4 + 1][t] = val.y;
            As[kq * 4 + 2][t] = val.z;
            As[kq * 4 + 3][t] = val.w;
        }
#pragma unroll
        for (int v = 0; v < 2; v++) {
            int idx = tid + v * 256;
            int k = idx >> 5, nq = idx & 31;
            *reinterpret_cast<float4*>(&Bs[k][nq * 4]) =
                *reinterpret_cast<const float4*>(&Wh_w[(size_t)(k0 - 256 + k) * HID + n0 + nq * 4]);
        }
        __syncthreads();
#pragma unroll
        for (int kk = 0; kk < 16; kk++) {
            float4 a0 = *reinterpret_cast<const float4*>(&As[kk][ty * 4]);
            float4 a1 = *reinterpret_cast<const float4*>(&As[kk][64 + ty * 4]);
            float a[8] = {a0.x, a0.y, a0.z, a0.w, a1.x, a1.y, a1.z, a1.w};
            float4 b0 = *reinterpret_cast<const float4*>(&Bs[kk][tx * 4]);
            float4 b1 = *reinterpret_cast<const float4*>(&Bs[kk][64 + tx * 4]);
            float bb[8] = {b0.x, b0.y, b0.z, b0.w, b1.x, b1.y, b1.z, b1.w};
#pragma unroll
            for (int i = 0; i < 8; i++)
#pragma unroll
                for (int j = 0; j < 8; j++)
                    acc[i][j] = fmaf(a[i], bb[j], acc[i][j]);
        }
        __syncthreads();
    }

    // -------- epilogue: bias + relu + store (and h_n for t == 511) ----------
    float bias[8];
#pragma unroll
    for (int j = 0; j < 4; j++) {
        bias[j]     = Wh_b[n0 + tx * 4 + j];
        bias[4 + j] = Wh_b[n0 + 64 + tx * 4 + j];
    }
#pragma unroll
    for (int i = 0; i < 8; i++) {
        int r = (i < 4) ? (ty * 4 + i) : (64 + ty * 4 + (i - 4));
        int t = t0 + r;
        float4 o0, o1;
        o0.x = fmaxf(acc[i][0] + bias[0], 0.f);
        o0.y = fmaxf(acc[i][1] + bias[1], 0.f);
        o0.z = fmaxf(acc[i][2] + bias[2], 0.f);
        o0.w = fmaxf(acc[i][3] + bias[3], 0.f);
        o1.x = fmaxf(acc[i][4] + bias[4], 0.f);
        o1.y = fmaxf(acc[i][5] + bias[5], 0.f);
        o1.z = fmaxf(acc[i][6] + bias[6], 0.f);
        o1.w = fmaxf(acc[i][7] + bias[7], 0.f);
        size_t row = ((size_t)bat * SEQ + t) * HID;
        *reinterpret_cast<float4*>(&out[row + n0 + tx * 4])      = o0;
        *reinterpret_cast<float4*>(&out[row + n0 + 64 + tx * 4]) = o1;
        if (write_hn && t == SEQ - 1) {
            float* hn = out + (size_t)BATCH * SEQ * HID;
            *reinterpret_cast<float4*>(&hn[(size_t)bat * HID + n0 + tx * 4])      = o0;
            *reinterpret_cast<float4*>(&hn[(size_t)bat * HID + n0 + 64 + tx * 4]) = o1;
        }
    }
}

// ----------------------------- launcher --------------------------------------
// Pure kernel launches — no runtime API calls, trivially graph-capturable.
extern "C" void kernel_launch(void* const* d_in, const int* in_sizes, int n_in,
                              void* d_out, int out_size)
{
    if (n_in < 7) return;
    const float* x    = (const float*)d_in[0];
    const float* Wu_w = (const float*)d_in[1];
    const float* Wu_b = (const float*)d_in[2];
    const float* Wh_w = (const float*)d_in[3];
    const float* Wh_b = (const float*)d_in[4];
    const float* A    = (const float*)d_in[5];
    const float* Bv   = (const float*)d_in[6];
    float* out = (float*)d_out;

    // u = relu(x @ Wu_w + b)
    k_u<<<BATCH * SEQ / 8, 256>>>(x, Wu_w, Wu_b);

    // P0 = A, HT[0] = B
    k_init<<<(MEM * MEM + 255) / 256, 256>>>(A, Bv);

    // Impulse response via doubling: HT rows [c,2c) = A^c @ HT rows [0,c)
    int which = 0;                       // current power lives in g_P0 (which=0) / g_P1 (which=1)
    for (int c = 1; c <= 256; c <<= 1) {
        k_extend<<<c, MEM>>>(which, c);
        if (c < 256) {
            k_sq<<<dim3(MEM / 64, MEM / 64), 256>>>(which);
            which ^= 1;
        }
    }

    // G = HT (512x256) @ Wh_w[0:256,:] (256x512)
    k_G<<<dim3(HID / 64, SEQ / 64), 256>>>(Wh_w);

    // h = relu([Toeplitz(u) | x] @ [G ; Wh_x] + bias), plus h_n slice
    int write_hn = (out_size >= BATCH * SEQ * HID + BATCH * HID) ? 1 : 0;
    k_big<<<dim3(HID / 128, SEQ / 128, BATCH), 256>>>(x, Wh_w, Wh_b, out, write_hn);
}

// round 4
// speedup vs baseline: 2.3578x; 2.3578x over previous
#include <cuda_runtime.h>
#include <cuda_bf16.h>
#include <cstdint>

#define BATCH 64
#define SEQ   512
#define DIN   512
#define MEM   256
#define HID   512

// ------------------------- device scratch (no allocs) ------------------------
__device__ float g_u[BATCH * SEQ];                 // u[b][t]
__device__ float g_HT[SEQ * MEM];                  // HT[t][k] = (A^t B)[k]
__device__ float g_P0[MEM * MEM], g_P0T[MEM * MEM];
__device__ float g_P1[MEM * MEM], g_P1T[MEM * MEM];
__device__ float g_WhmT[HID * MEM];                // Whm^T  [n][mem]
__device__ float g_G[SEQ * HID];                   // G[tau][n]
__device__ __nv_bfloat16 g_WtH[HID * 1024];        // W^T hi  [n][k]
__device__ __nv_bfloat16 g_WtL[HID * 1024];        // W^T lo

// ============================ helpers ========================================
__device__ __forceinline__ uint32_t smem_u32(const void* p) {
    uint32_t a;
    asm("{ .reg .u64 t; cvta.to.shared.u64 t, %1; cvt.u32.u64 %0, t; }"
        : "=r"(a) : "l"(p));
    return a;
}
__device__ __forceinline__ void ldsm_x4(uint32_t& a0, uint32_t& a1, uint32_t& a2,
                                        uint32_t& a3, uint32_t addr) {
    asm volatile("ldmatrix.sync.aligned.m8n8.x4.shared.b16 {%0,%1,%2,%3}, [%4];"
                 : "=r"(a0), "=r"(a1), "=r"(a2), "=r"(a3) : "r"(addr));
}
__device__ __forceinline__ void ldsm_x2(uint32_t& b0, uint32_t& b1, uint32_t addr) {
    asm volatile("ldmatrix.sync.aligned.m8n8.x2.shared.b16 {%0,%1}, [%2];"
                 : "=r"(b0), "=r"(b1) : "r"(addr));
}
__device__ __forceinline__ void mma_bf16(float* d, uint32_t a0, uint32_t a1,
                                         uint32_t a2, uint32_t a3,
                                         uint32_t b0, uint32_t b1) {
    asm volatile(
        "mma.sync.aligned.m16n8k16.row.col.f32.bf16.bf16.f32 "
        "{%0,%1,%2,%3}, {%4,%5,%6,%7}, {%8,%9}, {%0,%1,%2,%3};"
        : "+f"(d[0]), "+f"(d[1]), "+f"(d[2]), "+f"(d[3])
        : "r"(a0), "r"(a1), "r"(a2), "r"(a3), "r"(b0), "r"(b1));
}
// split f32 -> bf16 hi (truncate) + bf16 lo (truncate residual); pack 2 lanes
__device__ __forceinline__ void split2(float v0, float v1, uint32_t& hp, uint32_t& lp) {
    uint32_t b0 = __float_as_uint(v0), b1 = __float_as_uint(v1);
    hp = (b1 & 0xFFFF0000u) | (b0 >> 16);
    float r0 = v0 - __uint_as_float(b0 & 0xFFFF0000u);
    float r1 = v1 - __uint_as_float(b1 & 0xFFFF0000u);
    uint32_t c0 = __float_as_uint(r0), c1 = __float_as_uint(r1);
    lp = (c1 & 0xFFFF0000u) | (c0 >> 16);
}
#define SW64(b) ((b) ^ (((b) >> 3) & 0x30))

// ================= u = relu(x @ Wu_w + b), one warp per (b,t) ================
__global__ void k_u(const float* __restrict__ x, const float* __restrict__ w,
                    const float* __restrict__ bias)
{
    int warp = (blockIdx.x * blockDim.x + threadIdx.x) >> 5;
    int lane = threadIdx.x & 31;
    if (warp >= BATCH * SEQ) return;
    const float4* xr = reinterpret_cast<const float4*>(x) + (size_t)warp * (DIN / 4);
    const float4* wr = reinterpret_cast<const float4*>(w);
    float acc = 0.f;
#pragma unroll
    for (int i = 0; i < DIN / 4 / 32; i++) {
        float4 a = xr[lane + i * 32];
        float4 b = wr[lane + i * 32];
        acc += a.x * b.x + a.y * b.y + a.z * b.z + a.w * b.w;
    }
#pragma unroll
    for (int off = 16; off; off >>= 1) acc += __shfl_xor_sync(0xffffffffu, acc, off);
    if (lane == 0) g_u[warp] = fmaxf(acc + bias[0], 0.f);
}

// ========== k_init: P0 = A, P0T = A^T (tiled), HT[0] = B =====================
__global__ void k_init(const float* __restrict__ A, const float* __restrict__ Bv)
{
    __shared__ float s[32][33];
    int m0 = blockIdx.y * 32, n0 = blockIdx.x * 32;
    int tx = threadIdx.x & 31, ty = threadIdx.x >> 5;
#pragma unroll
    for (int q = 0; q < 4; q++) {
        int r = ty + 8 * q;
        float v = A[(m0 + r) * MEM + n0 + tx];
        g_P0[(m0 + r) * MEM + n0 + tx] = v;
        s[r][tx] = v;
    }
    __syncthreads();
#pragma unroll
    for (int q = 0; q < 4; q++) {
        int r = ty + 8 * q;
        g_P0T[(n0 + r) * MEM + m0 + tx] = s[tx][r];
    }
    if (blockIdx.x == 0 && blockIdx.y == 0 && threadIdx.x < MEM)
        g_HT[threadIdx.x] = Bv[threadIdx.x];
}

// ====== mmT core: C[m][n] = sum_k A[m][k]*B[n][k], 32x32 tile, 256 thr =======
__device__ __forceinline__ void mmT_core(
    const float* __restrict__ A, int lda,
    const float* __restrict__ B, int ldb,
    float* __restrict__ C, int ldc,
    int Mrows, int K, int m0, int n0,
    float* __restrict__ CT, int ldct)
{
    __shared__ float sA[32][65];
    __shared__ float sB[32][65];
    int t = threadIdx.x, tx = t & 31, ty = t >> 5;
    float acc[4] = {0.f, 0.f, 0.f, 0.f};
    for (int k0 = 0; k0 < K; k0 += 64) {
#pragma unroll
        for (int i = 0; i < 8; i++) {
            int id = t + i * 256;
            int r = id >> 6, kk = id & 63;
            sA[r][kk] = (m0 + r < Mrows) ? A[(size_t)(m0 + r) * lda + k0 + kk] : 0.f;
            sB[r][kk] = B[(size_t)(n0 + r) * ldb + k0 + kk];
        }
        __syncthreads();
#pragma unroll
        for (int kk = 0; kk < 64; kk++) {
            float b = sB[tx][kk];
#pragma unroll
            for (int q = 0; q < 4; q++)
                acc[q] = fmaf(sA[ty + 8 * q][kk], b, acc[q]);
        }
        __syncthreads();
    }
#pragma unroll
    for (int q = 0; q < 4; q++) {
        int r = ty + 8 * q;
        if (m0 + r < Mrows) C[(size_t)(m0 + r) * ldc + n0 + tx] = acc[q];
    }
    if (CT) {
#pragma unroll
        for (int q = 0; q < 4; q++) sA[ty + 8 * q][tx] = acc[q];
        __syncthreads();
#pragma unroll
        for (int q = 0; q < 4; q++) {
            int r = ty + 8 * q;
            CT[(size_t)(n0 + r) * ldct + m0 + tx] = sA[tx][r];
        }
    }
}

// ====== fused doubling step: square (c<256) + extend in one launch ===========
// blocks [0,64): square P^2 -> other buffer (skipped when c==256)
// blocks [off,..): extend HT[c+r] = HT[r] @ P^T
__global__ __launch_bounds__(256) void k_step(int which, int c)
{
    int nsq = (c < 256) ? 64 : 0;
    if ((int)blockIdx.x < nsq) {
        const float* P  = which ? g_P1  : g_P0;
        const float* PT = which ? g_P1T : g_P0T;
        float* D  = which ? g_P0  : g_P1;
        float* DT = which ? g_P0T : g_P1T;
        mmT_core(P, MEM, PT, MEM, D, MEM, MEM, MEM,
                 (blockIdx.x >> 3) * 32, (blockIdx.x & 7) * 32, DT, MEM);
    } else {
        int id = blockIdx.x - nsq;
        const float* P = which ? g_P1 : g_P0;
        mmT_core(g_HT, MEM, P, MEM, g_HT + (size_t)c * MEM, MEM, c, MEM,
                 (id >> 3) * 32, (id & 7) * 32, nullptr, 0);
    }
}

// WhmT[n][mem] = Wh_w[mem][n]
__global__ void k_tr(const float* __restrict__ Wh_w)
{
    __shared__ float s[32][33];
    int m0 = blockIdx.y * 32, n0 = blockIdx.x * 32;
    int tx = threadIdx.x & 31, ty = threadIdx.x >> 5;
#pragma unroll
    for (int q = 0; q < 4; q++) {
        int r = ty + 8 * q;
        s[r][tx] = Wh_w[(m0 + r) * HID + n0 + tx];
    }
    __syncthreads();
#pragma unroll
    for (int q = 0; q < 4; q++) {
        int r = ty + 8 * q;
        g_WhmT[(n0 + r) * MEM + m0 + tx] = s[tx][r];
    }
}

// G = HT @ Whm via A@B^T with B = WhmT
__global__ __launch_bounds__(256) void k_GT()
{
    mmT_core(g_HT, MEM, g_WhmT, MEM, g_G, HID, SEQ, MEM,
             blockIdx.y * 32, blockIdx.x * 32, nullptr, 0);
}

// Wt[n][k] = (k<512 ? G[k][n] : Wh_w[256+k-512][n]), split hi/lo bf16
__global__ void k_prepW(const float* __restrict__ Wh_w)
{
    __shared__ float s[32][33];
    int k0 = blockIdx.x * 32, n0 = blockIdx.y * 32;
    int tx = threadIdx.x & 31, ty = threadIdx.x >> 5;
#pragma unroll
    for (int q = 0; q < 4; q++) {
        int k = k0 + ty + 8 * q;
        float v = (k < 512) ? g_G[(size_t)k * HID + n0 + tx]
                            : Wh_w[(size_t)(k - 256) * HID + n0 + tx];
        s[ty + 8 * q][tx] = v;
    }
    __syncthreads();
#pragma unroll
    for (int q = 0; q < 4; q++) {
        int nn = ty + 8 * q;
        float v = s[tx][nn];
        uint32_t b = __float_as_uint(v);
        float r = v - __uint_as_float(b & 0xFFFF0000u);
        uint32_t c = __float_as_uint(r);
        size_t off = (size_t)(n0 + nn) * 1024 + k0 + tx;
        reinterpret_cast<unsigned short*>(g_WtH)[off] = (unsigned short)(b >> 16);
        reinterpret_cast<unsigned short*>(g_WtL)[off] = (unsigned short)(c >> 16);
    }
}

// ===================== big fused GEMM via mma.sync bf16 ======================
// out[b][t][n] = relu( Toep(u)@G + x@Whx + bias );  M=N=128 tile, K chunks 32.
// 8 warps: 2 warp-rows (64 t) x 4 warp-cols (32 n); warp tile 64x32.
// bf16 split: acc += Ahi*Bhi + Ahi*Blo + Alo*Bhi  (3 passes, shared frags).
__global__ __launch_bounds__(256, 1) void k_big_mma(
    const float* __restrict__ x,
    const float* __restrict__ Wh_b,
    float* __restrict__ out, int write_hn)
{
    __shared__ float s_u[1024];                 // [0,512)=0 pad, [512,1024)=u
    __shared__ float s_b[128];
    __shared__ __align__(128) char sAhi[128 * 64];
    __shared__ __align__(128) char sAlo[128 * 64];
    __shared__ __align__(128) char sBhi[128 * 64];
    __shared__ __align__(128) char sBlo[128 * 64];

    int tid = threadIdx.x;
    int wid = tid >> 5, lane = tid & 31;
    int bat = blockIdx.z, t0 = blockIdx.y * 128, n0 = blockIdx.x * 128;
    int wr = wid >> 2, wc = wid & 3;            // warp row/col

    for (int i = tid; i < 512; i += 256) {
        s_u[i] = 0.f;
        s_u[512 + i] = g_u[bat * SEQ + i];
    }
    if (tid < 128) s_b[tid] = Wh_b[n0 + tid];

    uint32_t uAhi = smem_u32(sAhi), uAlo = smem_u32(sAlo);
    uint32_t uBhi = smem_u32(sBhi), uBlo = smem_u32(sBlo);

    float acc[4][4][4];
#pragma unroll
    for (int i = 0; i < 4; i++)
#pragma unroll
        for (int j = 0; j < 4; j++)
#pragma unroll
            for (int q = 0; q < 4; q++) acc[i][j][q] = 0.f;

    __syncthreads();

    int kcmax1 = t0 / 32 + 4;                   // causal bound for phase-1 chunks
    for (int kc = 0; kc < 32; kc++) {
        if (kc < 16 && kc >= kcmax1) continue;

        // ---------------- stage A (hi/lo) ----------------------------------
#pragma unroll
        for (int i = 0; i < 8; i++) {
            int pid = tid + i * 256;            // 0..2047
            int row = pid >> 4, kp = pid & 15;  // k = 2*kp
            float v0, v1;
            if (kc < 16) {
                int idx = 512 + t0 + row - kc * 32 - kp * 2;
                v0 = s_u[idx];
                v1 = s_u[idx - 1];
            } else {
                const float2 xv = *reinterpret_cast<const float2*>(
                    &x[((size_t)(bat * SEQ) + t0 + row) * DIN + (kc - 16) * 32 + kp * 2]);
                v0 = xv.x; v1 = xv.y;
            }
            uint32_t hp, lp;
            split2(v0, v1, hp, lp);
            int sw = SW64(row * 64 + kp * 4);
            *reinterpret_cast<uint32_t*>(sAhi + sw) = hp;
            *reinterpret_cast<uint32_t*>(sAlo + sw) = lp;
        }
        // ---------------- stage B (hi/lo) from Wt --------------------------
#pragma unroll
        for (int i = 0; i < 8; i++) {
            int pid = tid + i * 256;
            int row = pid >> 4, kp = pid & 15;
            size_t off = (size_t)(n0 + row) * 1024 + kc * 32 + kp * 2;
            uint32_t bh = *reinterpret_cast<const uint32_t*>(
                reinterpret_cast<const unsigned short*>(g_WtH) + off);
            uint32_t bl = *reinterpret_cast<const uint32_t*>(
                reinterpret_cast<const unsigned short*>(g_WtL) + off);
            int sw = SW64(row * 64 + kp * 4);
            *reinterpret_cast<uint32_t*>(sBhi + sw) = bh;
            *reinterpret_cast<uint32_t*>(sBlo + sw) = bl;
        }
        __syncthreads();

        // ---------------- compute: 2 k-steps of 16 -------------------------
#pragma unroll
        for (int ks = 0; ks < 2; ks++) {
            uint32_t ah[4][4], al[4][4], bh[4][2], bl[4][2];
            int arow = wr * 64 + (lane & 15);
            int akb  = ks * 32 + (lane >> 4) * 16;
#pragma unroll
            for (int mf = 0; mf < 4; mf++) {
                int sw = SW64((arow + mf * 16) * 64 + akb);
                ldsm_x4(ah[mf][0], ah[mf][1], ah[mf][2], ah[mf][3], uAhi + sw);
                ldsm_x4(al[mf][0], al[mf][1], al[mf][2], al[mf][3], uAlo + sw);
            }
            int brow = wc * 32 + (lane & 7);
            int bkb  = ks * 32 + ((lane >> 3) & 1) * 16;
#pragma unroll
            for (int nf = 0; nf < 4; nf++) {
                int sw = SW64((brow + nf * 8) * 64 + bkb);
                ldsm_x2(bh[nf][0], bh[nf][1], uBhi + sw);
                ldsm_x2(bl[nf][0], bl[nf][1], uBlo + sw);
            }
#pragma unroll
            for (int mf = 0; mf < 4; mf++)
#pragma unroll
                for (int nf = 0; nf < 4; nf++) {
                    mma_bf16(acc[mf][nf], ah[mf][0], ah[mf][1], ah[mf][2], ah[mf][3],
                             bh[nf][0], bh[nf][1]);
                    mma_bf16(acc[mf][nf], ah[mf][0], ah[mf][1], ah[mf][2], ah[mf][3],
                             bl[nf][0], bl[nf][1]);
                    mma_bf16(acc[mf][nf], al[mf][0], al[mf][1], al[mf][2], al[mf][3],
                             bh[nf][0], bh[nf][1]);
                }
        }
        __syncthreads();
    }

    // ---------------- epilogue: bias + relu + store ------------------------
    float* hn = out + (size_t)BATCH * SEQ * HID;
#pragma unroll
    for (int mf = 0; mf < 4; mf++) {
        int m = wr * 64 + mf * 16 + (lane >> 2);
        int t1 = t0 + m, t2 = t0 + m + 8;
        size_t r1 = ((size_t)bat * SEQ + t1) * HID;
        size_t r2 = ((size_t)bat * SEQ + t2) * HID;
#pragma unroll
        for (int nf = 0; nf < 4; nf++) {
            int cl = wc * 32 + nf * 8 + (lane & 3) * 2;   // col within tile
            float2 v0, v1;
            v0.x = fmaxf(acc[mf][nf][0] + s_b[cl],     0.f);
            v0.y = fmaxf(acc[mf][nf][1] + s_b[cl + 1], 0.f);
            v1.x = fmaxf(acc[mf][nf][2] + s_b[cl],     0.f);
            v1.y = fmaxf(acc[mf][nf][3] + s_b[cl + 1], 0.f);
            *reinterpret_cast<float2*>(&out[r1 + n0 + cl]) = v0;
            *reinterpret_cast<float2*>(&out[r2 + n0 + cl]) = v1;
            if (write_hn) {
                if (t1 == SEQ - 1)
                    *reinterpret_cast<float2*>(&hn[(size_t)bat * HID + n0 + cl]) = v0;
                if (t2 == SEQ - 1)
                    *reinterpret_cast<float2*>(&hn[(size_t)bat * HID + n0 + cl]) = v1;
            }
        }
    }
}

// ----------------------------- launcher --------------------------------------
extern "C" void kernel_launch(void* const* d_in, const int* in_sizes, int n_in,
                              void* d_out, int out_size)
{
    if (n_in < 7) return;
    const float* x    = (const float*)d_in[0];
    const float* Wu_w = (const float*)d_in[1];
    const float* Wu_b = (const float*)d_in[2];
    const float* Wh_w = (const float*)d_in[3];
    const float* Wh_b = (const float*)d_in[4];
    const float* A    = (const float*)d_in[5];
    const float* Bv   = (const float*)d_in[6];
    float* out = (float*)d_out;

    k_u<<<BATCH * SEQ / 8, 256>>>(x, Wu_w, Wu_b);
    k_init<<<dim3(8, 8), 256>>>(A, Bv);

    int which = 0;
    for (int c = 1; c <= 256; c <<= 1) {
        int nsq = (c < 256) ? 64 : 0;
        int next = nsq + 8 * ((c + 31) / 32);
        k_step<<<next, 256>>>(which, c);
        if (c < 256) which ^= 1;
    }

    k_tr<<<dim3(16, 8), 256>>>(Wh_w);
    k_GT<<<dim3(16, 16), 256>>>();
    k_prepW<<<dim3(32, 16), 256>>>(Wh_w);

    int write_hn = (out_size >= BATCH * SEQ * HID + BATCH * HID) ? 1 : 0;
    k_big_mma<<<dim3(4, 4, 64), 256>>>(x, Wh_b, out, write_hn);
}